// round 2
// baseline (speedup 1.0000x reference)
#include <cuda_runtime.h>

// Batched Chamfer loss, B=16, N=M=4096, 3D points.
// d2(n,m) = ||s||^2 + ||t||^2 - 2 s.t ; per-pair inner loop is 3 FFMA + 1 FMNMX
// by pre-folding (-2x,-2y,-2z, norm2) into the shared-memory database tile.

constexpr int B_  = 16;
constexpr int N_  = 4096;   // == M_
constexpr int BS  = 256;    // threads per block
constexpr int R   = 2;      // query points per thread
constexpr int TILE = 1024;  // database points per smem tile
constexpr int CHUNKS = N_ / (BS * R);   // 8 query chunks per (batch, dir)
constexpr int NPART  = 2 * B_ * CHUNKS; // 256 partials

__device__ float g_partial[NPART];

__global__ void __launch_bounds__(BS)
chamfer_kernel(const float* __restrict__ src, const float* __restrict__ tgt)
{
    const int dir = blockIdx.z;                 // 0: src->tgt, 1: tgt->src
    const float* __restrict__ q  = (dir == 0) ? src : tgt;
    const float* __restrict__ db = (dir == 0) ? tgt : src;
    const int b   = blockIdx.y;
    const int tid = threadIdx.x;

    __shared__ float4 s_db[TILE];
    __shared__ float  s_red[BS];

    // Load R query points per thread, precompute squared norms.
    float qx[R], qy[R], qz[R], q2[R], vmin[R];
#pragma unroll
    for (int r = 0; r < R; ++r) {
        const int n = blockIdx.x * (BS * R) + r * BS + tid;
        const float* p = q + ((size_t)b * N_ + n) * 3;
        qx[r] = p[0]; qy[r] = p[1]; qz[r] = p[2];
        q2[r] = qx[r] * qx[r] + qy[r] * qy[r] + qz[r] * qz[r];
        vmin[r] = 3.4e38f;
    }

    for (int t0 = 0; t0 < N_; t0 += TILE) {
        __syncthreads();
        // Cooperative tile fill: (-2x, -2y, -2z, x^2+y^2+z^2)
        for (int i = tid; i < TILE; i += BS) {
            const float* p = db + ((size_t)b * N_ + t0 + i) * 3;
            const float x = p[0], y = p[1], z = p[2];
            s_db[i] = make_float4(-2.0f * x, -2.0f * y, -2.0f * z,
                                  x * x + y * y + z * z);
        }
        __syncthreads();

#pragma unroll 8
        for (int m = 0; m < TILE; ++m) {
            const float4 t = s_db[m];   // broadcast LDS.128, conflict-free
#pragma unroll
            for (int r = 0; r < R; ++r) {
                const float v = fmaf(qx[r], t.x,
                                fmaf(qy[r], t.y,
                                fmaf(qz[r], t.z, t.w)));
                vmin[r] = fminf(vmin[r], v);
            }
        }
    }

    // Per-thread: sum of clamped nearest-neighbor squared distances.
    float acc = 0.0f;
#pragma unroll
    for (int r = 0; r < R; ++r)
        acc += fmaxf(q2[r] + vmin[r], 0.0f);

    // Deterministic block reduction.
    s_red[tid] = acc;
    __syncthreads();
#pragma unroll
    for (int s = BS / 2; s > 0; s >>= 1) {
        if (tid < s) s_red[tid] += s_red[tid + s];
        __syncthreads();
    }
    if (tid == 0)
        g_partial[dir * (B_ * CHUNKS) + b * CHUNKS + blockIdx.x] = s_red[0];
}

__global__ void __launch_bounds__(NPART)
finalize_kernel(const float* __restrict__ weights, float* __restrict__ out)
{
    const int t = threadIdx.x;          // 0..255, one partial each
    __shared__ float s[NPART];
    // partial index: dir*128 + b*8 + chunk  -> b = (t & 127) >> 3
    const int b = (t & 127) >> 3;
    // loss = (1/B) * sum_b w_b * (mean_n dmin + mean_m dmin); N == M == 4096
    s[t] = g_partial[t] * weights[b] * (1.0f / (16.0f * 4096.0f));
    __syncthreads();
#pragma unroll
    for (int st = NPART / 2; st > 0; st >>= 1) {
        if (t < st) s[t] += s[t + st];
        __syncthreads();
    }
    if (t == 0) out[0] = s[0];
}

extern "C" void kernel_launch(void* const* d_in, const int* in_sizes, int n_in,
                              void* d_out, int out_size)
{
    const float* src = (const float*)d_in[0];   // [16, 4096, 3]
    const float* tgt = (const float*)d_in[1];   // [16, 4096, 3]
    const float* w   = (const float*)d_in[2];   // [16]

    dim3 grid(CHUNKS, B_, 2);                   // 8 x 16 x 2 = 256 blocks
    chamfer_kernel<<<grid, BS>>>(src, tgt);
    finalize_kernel<<<1, NPART>>>(w, (float*)d_out);
}

// round 5
// speedup vs baseline: 1.1992x; 1.1992x over previous
#include <cuda_runtime.h>

// Batched Chamfer loss, B=16, N=M=4096, 3D points.
// d2(n,m) = ||s||^2 + (||t||^2 - 2 s.t); inner loop uses packed fp32x2 FFMA2:
// database tile pre-packed in smem as pairs (-2x, -2y, -2z, |t|^2) x2, so each
// (query, db-pair) costs 3 FFMA2 (fma pipe) + 2 FMNMX (alu pipe).

constexpr int B_    = 16;
constexpr int N_    = 4096;            // == M
constexpr int BS    = 256;             // threads per block
constexpr int R     = 2;               // query points per thread
constexpr int TILE  = 1024;            // database points per smem tile
constexpr int PAIRS = TILE / 2;        // packed db pairs per tile
constexpr int CHUNKS = N_ / (BS * R);  // 8 query chunks per (batch, dir)
constexpr int NPART  = 2 * B_ * CHUNKS;// 256 partials

__device__ float g_partial[NPART];

using u64 = unsigned long long;

__device__ __forceinline__ u64 fma2(u64 a, u64 b, u64 c) {
    u64 d;
    asm("fma.rn.f32x2 %0, %1, %2, %3;" : "=l"(d) : "l"(a), "l"(b), "l"(c));
    return d;
}
__device__ __forceinline__ u64 pack2(float a, float b) {
    u64 d;
    asm("mov.b64 %0, {%1, %2};" : "=l"(d) : "f"(a), "f"(b));
    return d;
}
__device__ __forceinline__ void unpack2(u64 v, float& lo, float& hi) {
    asm("mov.b64 {%0, %1}, %2;" : "=f"(lo), "=f"(hi) : "l"(v));
}

__global__ void __launch_bounds__(BS)
chamfer_kernel(const float* __restrict__ src, const float* __restrict__ tgt)
{
    const int dir = blockIdx.z;                 // 0: src->tgt, 1: tgt->src
    const float* __restrict__ q  = (dir == 0) ? src : tgt;
    const float* __restrict__ db = (dir == 0) ? tgt : src;
    const int b   = blockIdx.y;
    const int tid = threadIdx.x;

    __shared__ ulonglong2 sA[PAIRS];   // {pack(-2x0,-2x1), pack(-2y0,-2y1)}
    __shared__ ulonglong2 sB[PAIRS];   // {pack(-2z0,-2z1), pack(w0,w1)}
    __shared__ float s_red[BS];

    // Load R query points per thread; splat each coord into both f32x2 halves.
    u64 qx2[R], qy2[R], qz2[R];
    float q2[R], vlo[R], vhi[R];
#pragma unroll
    for (int r = 0; r < R; ++r) {
        const int n = blockIdx.x * (BS * R) + r * BS + tid;
        const float* p = q + ((size_t)b * N_ + n) * 3;
        const float x = p[0], y = p[1], z = p[2];
        qx2[r] = pack2(x, x);
        qy2[r] = pack2(y, y);
        qz2[r] = pack2(z, z);
        q2[r]  = x * x + y * y + z * z;
        vlo[r] = 3.4e38f;
        vhi[r] = 3.4e38f;
    }

    for (int t0 = 0; t0 < N_; t0 += TILE) {
        __syncthreads();
        // Cooperative packed tile fill: 2 db points per slot.
        for (int j = tid; j < PAIRS; j += BS) {
            const float* p = db + ((size_t)b * N_ + t0 + 2 * j) * 3;
            const float x0 = p[0], y0 = p[1], z0 = p[2];
            const float x1 = p[3], y1 = p[4], z1 = p[5];
            ulonglong2 A, Bv;
            A.x  = pack2(-2.0f * x0, -2.0f * x1);
            A.y  = pack2(-2.0f * y0, -2.0f * y1);
            Bv.x = pack2(-2.0f * z0, -2.0f * z1);
            Bv.y = pack2(x0 * x0 + y0 * y0 + z0 * z0,
                         x1 * x1 + y1 * y1 + z1 * z1);
            sA[j] = A;
            sB[j] = Bv;
        }
        __syncthreads();

#pragma unroll 8
        for (int j = 0; j < PAIRS; ++j) {
            const ulonglong2 A  = sA[j];   // LDS.128 broadcast
            const ulonglong2 Bv = sB[j];   // LDS.128 broadcast
#pragma unroll
            for (int r = 0; r < R; ++r) {
                const u64 v = fma2(qx2[r], A.x,
                              fma2(qy2[r], A.y,
                              fma2(qz2[r], Bv.x, Bv.y)));
                float lo, hi;
                unpack2(v, lo, hi);
                vlo[r] = fminf(vlo[r], lo);
                vhi[r] = fminf(vhi[r], hi);
            }
        }
    }

    // Per-thread: sum of clamped nearest-neighbor squared distances.
    float acc = 0.0f;
#pragma unroll
    for (int r = 0; r < R; ++r)
        acc += fmaxf(q2[r] + fminf(vlo[r], vhi[r]), 0.0f);

    // Deterministic block reduction.
    s_red[tid] = acc;
    __syncthreads();
#pragma unroll
    for (int s = BS / 2; s > 0; s >>= 1) {
        if (tid < s) s_red[tid] += s_red[tid + s];
        __syncthreads();
    }
    if (tid == 0)
        g_partial[dir * (B_ * CHUNKS) + b * CHUNKS + blockIdx.x] = s_red[0];
}

__global__ void __launch_bounds__(NPART)
finalize_kernel(const float* __restrict__ weights, float* __restrict__ out)
{
    const int t = threadIdx.x;          // 0..255, one partial each
    __shared__ float s[NPART];
    const int b = (t & 127) >> 3;       // partial index: dir*128 + b*8 + chunk
    // loss = (1/B) * sum_b w_b * (mean_n dmin + mean_m dmin); N == M == 4096
    s[t] = g_partial[t] * weights[b] * (1.0f / (16.0f * 4096.0f));
    __syncthreads();
#pragma unroll
    for (int st = NPART / 2; st > 0; st >>= 1) {
        if (t < st) s[t] += s[t + st];
        __syncthreads();
    }
    if (t == 0) out[0] = s[0];
}

extern "C" void kernel_launch(void* const* d_in, const int* in_sizes, int n_in,
                              void* d_out, int out_size)
{
    const float* src = (const float*)d_in[0];   // [16, 4096, 3]
    const float* tgt = (const float*)d_in[1];   // [16, 4096, 3]
    const float* w   = (const float*)d_in[2];   // [16]

    dim3 grid(CHUNKS, B_, 2);                   // 8 x 16 x 2 = 256 blocks
    chamfer_kernel<<<grid, BS>>>(src, tgt);
    finalize_kernel<<<1, NPART>>>(w, (float*)d_out);
}